// round 15
// baseline (speedup 1.0000x reference)
#include <cuda_runtime.h>
#include <math.h>
#include <stdint.h>

#define IMG_W 4096
#define IMG_H 4096

#define BX 32
#define BY 8
#define TX 4
#define TY 16
#define GRID_X (IMG_W / (BX * TX))        // 32
#define GRID_Y (IMG_H / (BY * TY))        // 32
#define N_EDGE_BLOCKS (GRID_X * GRID_Y)   // 1024

#define KD_BLOCKS 64
#define TOTAL_BLOCKS (KD_BLOCKS + N_EDGE_BLOCKS)

#define DEPTH 5            // smem ring depth (rows in flight per warp)
#define ROWF 132           // floats per staged row: [0..127]=px, 128=L, 129=R, 2 pad

__device__ float g_edge_partials[N_EDGE_BLOCKS];
__device__ float g_kd_partials[KD_BLOCKS];
__device__ unsigned int g_done_count;

typedef unsigned long long u64;

// ---- packed f32x2 helpers ----
__device__ __forceinline__ u64 pack2(float lo, float hi) {
    u64 r; asm("mov.b64 %0, {%1, %2};" : "=l"(r) : "f"(lo), "f"(hi)); return r;
}
__device__ __forceinline__ void unpack2(u64 v, float& lo, float& hi) {
    asm("mov.b64 {%0, %1}, %2;" : "=f"(lo), "=f"(hi) : "l"(v));
}
__device__ __forceinline__ u64 add2(u64 a, u64 b) {
    u64 r; asm("add.rn.f32x2 %0, %1, %2;" : "=l"(r) : "l"(a), "l"(b)); return r;
}
__device__ __forceinline__ u64 mul2(u64 a, u64 b) {
    u64 r; asm("mul.rn.f32x2 %0, %1, %2;" : "=l"(r) : "l"(a), "l"(b)); return r;
}
__device__ __forceinline__ u64 fma2(u64 a, u64 b, u64 c) {
    u64 r; asm("fma.rn.f32x2 %0, %1, %2, %3;" : "=l"(r) : "l"(a), "l"(b), "l"(c)); return r;
}

__device__ __forceinline__ float fsqrt_approx(float x) {
    float r; asm("sqrt.approx.f32 %0, %1;" : "=f"(r) : "f"(x)); return r;
}

__device__ __forceinline__ float warp_reduce_sum(float v) {
#pragma unroll
    for (int off = 16; off > 0; off >>= 1)
        v += __shfl_down_sync(0xFFFFFFFFu, v, off);
    return v;
}

// ---- cp.async primitives ----
__device__ __forceinline__ void cp16(uint32_t dst, const float* src) {
    asm volatile("cp.async.cg.shared.global [%0], [%1], 16;" :: "r"(dst), "l"(src));
}
__device__ __forceinline__ void cp4(uint32_t dst, const float* src) {
    asm volatile("cp.async.ca.shared.global [%0], [%1], 4;" :: "r"(dst), "l"(src));
}
__device__ __forceinline__ void cp_commit() {
    asm volatile("cp.async.commit_group;" ::: "memory");
}
__device__ __forceinline__ void cp_wait_3() {
    asm volatile("cp.async.wait_group 3;" ::: "memory");   // DEPTH-2
}

// Sobel edge at (y,x) from zero-padded seg (kd path, scattered)
__device__ __forceinline__ float edge_at(const float* __restrict__ seg, int y, int x) {
    float v[3][3];
#pragma unroll
    for (int dy = 0; dy < 3; dy++)
#pragma unroll
        for (int dx = 0; dx < 3; dx++) {
            int yy = y - 1 + dy, xx = x - 1 + dx;
            v[dy][dx] = ((unsigned)yy < (unsigned)IMG_H && (unsigned)xx < (unsigned)IMG_W)
                        ? __ldg(seg + (size_t)yy * IMG_W + xx) : 0.0f;
        }
    float ex = (v[0][2] + 2.0f * v[1][2] + v[2][2]) - (v[0][0] + 2.0f * v[1][0] + v[2][0]);
    float ey = (v[2][0] + 2.0f * v[2][1] + v[2][2]) - (v[0][0] + 2.0f * v[0][1] + v[0][2]);
    return fsqrt_approx(ex * ex + ey * ey);
}

// ---------------------------------------------------------------------------
__global__ __launch_bounds__(256, 4)
void fused_kernel(const float* __restrict__ pred, const float* __restrict__ tgt,
                  const float* __restrict__ kp, int K, float* __restrict__ out) {
    const int tid = threadIdx.x;
    const int lane = tid & 31;
    const int wid  = tid >> 5;
    float acc = 0.0f;
    __shared__ float sred[8];
    __shared__ bool s_last;
    __shared__ __align__(16) float s_ring[8 * DEPTH * 2 * ROWF];   // 42.2 KB

    if (blockIdx.x < KD_BLOCKS) {
        // ---- keypoint path: kd(k) = sum_{du,dv in -1..2} Wx*Wy*edge ----
        const int idx = blockIdx.x * 256 + tid;
        const int k    = idx >> 4;
        const int cell = idx & 15;
        if (k < K) {
            float gx = __ldg(kp + 2 * k);
            float gy = __ldg(kp + 2 * k + 1);
            float fx = (gx + 1.0f) * (IMG_W * 0.5f) - 0.5f;
            float fy = (gy + 1.0f) * (IMG_H * 0.5f) - 0.5f;
            float flx = floorf(fx), fly = floorf(fy);
            int x0 = (int)flx, y0 = (int)fly;
            float wx1 = fx - flx, wy1 = fy - fly;
            float wx0 = 1.0f - wx1, wy0 = 1.0f - wy1;
            float ax0 = ((unsigned)x0 < (unsigned)IMG_W) ? wx0 : 0.0f;
            float ax1 = ((unsigned)(x0 + 1) < (unsigned)IMG_W) ? wx1 : 0.0f;
            float ay0 = ((unsigned)y0 < (unsigned)IMG_H) ? wy0 : 0.0f;
            float ay1 = ((unsigned)(y0 + 1) < (unsigned)IMG_H) ? wy1 : 0.0f;

            int du = (cell & 3) - 1;
            int dv = (cell >> 2) - 1;
            float Wx = ((du <= 1) ? ax0 : 0.0f) + ((du >= 0) ? ax1 : 0.0f);
            float Wy = ((dv <= 1) ? ay0 : 0.0f) + ((dv >= 0) ? ay1 : 0.0f);
            float W = Wx * Wy;
            int cx = x0 + du, cy = y0 + dv;
            if (W != 0.0f && (unsigned)cx < (unsigned)IMG_W && (unsigned)cy < (unsigned)IMG_H)
                acc = W * edge_at(pred, cy, cx);
        }
        float ws = warp_reduce_sum(acc);
        if (lane == 0) sred[wid] = ws;
        __syncthreads();
        if (wid == 0) {
            float v = (lane < 8) ? sred[lane] : 0.0f;
            v = warp_reduce_sum(v);
            if (lane == 0) g_kd_partials[blockIdx.x] = v;
        }
    } else {
        // ---- edge-loss path: cp.async smem ring (depth 5) + packed f32x2 ----
        const int bid = blockIdx.x - KD_BLOCKS;
        const int bx = bid % GRID_X;
        const int by = bid / GRID_X;
        const int xbase = bx * (BX * TX);             // warp's 128-px segment
        const int y0 = (by * BY + wid) * TY;

        float* ring = &s_ring[wid * (DEPTH * 2 * ROWF)];
        const uint32_t ring_sa = (uint32_t)__cvta_generic_to_shared(ring);

        const int li = (lane == 0)  ? 128 : 4 * lane - 1;
        const int ri = (lane == 31) ? 129 : 4 * lane + 4;

        auto issue_row = [&](int row, int slot) {
            float* sp = ring + slot * (2 * ROWF);
            float* st = sp + ROWF;
            uint32_t spa = ring_sa + slot * (2 * ROWF) * 4;
            uint32_t sta = spa + ROWF * 4;
            if ((unsigned)row < (unsigned)IMG_H) {
                const float* pp = pred + (size_t)row * IMG_W + xbase;
                const float* tp = tgt  + (size_t)row * IMG_W + xbase;
                cp16(spa + 16u * lane, pp + 4 * lane);
                cp16(sta + 16u * lane, tp + 4 * lane);
                if (lane == 0) {
                    if (xbase > 0) { cp4(spa + 128 * 4, pp - 1); cp4(sta + 128 * 4, tp - 1); }
                    else           { sp[128] = 0.0f; st[128] = 0.0f; }
                }
                if (lane == 1) {
                    if (xbase + 128 < IMG_W) { cp4(spa + 129 * 4, pp + 128); cp4(sta + 129 * 4, tp + 128); }
                    else                     { sp[129] = 0.0f; st[129] = 0.0f; }
                }
            } else {
                float4 z = make_float4(0.f, 0.f, 0.f, 0.f);
                *(float4*)(sp + 4 * lane) = z;
                *(float4*)(st + 4 * lane) = z;
                if (lane == 0) { sp[128] = 0.f; st[128] = 0.f; }
                if (lane == 1) { sp[129] = 0.f; st[129] = 0.f; }
            }
            cp_commit();
        };

        auto consume_row = [&](int slot, u64 dst[6]) {
            const float* sp = ring + slot * (2 * ROWF);
            const float* st = sp + ROWF;
            float4 pv = *(const float4*)(sp + 4 * lane);
            float4 tv = *(const float4*)(st + 4 * lane);
            float pl = sp[li], pr = sp[ri];
            float tl = st[li], tr = st[ri];
            dst[0] = pack2(pl, tl);
            dst[1] = pack2(pv.x, tv.x); dst[2] = pack2(pv.y, tv.y);
            dst[3] = pack2(pv.z, tv.z); dst[4] = pack2(pv.w, tv.w);
            dst[5] = pack2(pr, tr);
        };

        // prologue: rows y0-1 .. y0+3 into slots 0..4 (row r -> slot (r-y0+1)%5)
#pragma unroll
        for (int g = 0; g < DEPTH; g++)
            issue_row(y0 - 1 + g, g);

        const u64 TWO2  = pack2(2.0f, 2.0f);
        const u64 NEG12 = pack2(-1.0f, -1.0f);

        u64 acc2 = 0;          // packed (sum P, sum T)
        float accD = 0.0f;     // sum sqrt(P*T)

        u64 PT[3][6];
        cp_wait_3();          // groups 0,1 complete
        __syncwarp();
        consume_row(0, PT[0]);   // row y0-1
        consume_row(1, PT[1]);   // row y0

#pragma unroll
        for (int t = 0; t < TY; t++) {
            const int am = t % 3, bm = (t + 1) % 3, cm = (t + 2) % 3;
            // issue row y0+t+4 into slot (t+5)%5 = t%5 (skip past bottom halo)
            if (t <= TY - 4) issue_row(y0 + 4 + t, t % DEPTH);
            else             cp_commit();      // empty group keeps accounting
            cp_wait_3();                        // groups <= t+2 complete
            __syncwarp();
            consume_row((t + 2) % DEPTH, PT[cm]);  // row y0+t+1

            const u64* ra = PT[am]; const u64* rb = PT[bm]; const u64* rc = PT[cm];
            u64 cs[6], dd[6];
#pragma unroll
            for (int i = 0; i < 6; i++) {
                cs[i] = add2(fma2(rb[i], TWO2, ra[i]), rc[i]);   // a + 2b + c
                dd[i] = fma2(ra[i], NEG12, rc[i]);               // c - a
            }
#pragma unroll
            for (int j = 0; j < 4; j++) {
                u64 ex = fma2(cs[j], NEG12, cs[j + 2]);
                u64 ey = add2(fma2(dd[j + 1], TWO2, dd[j]), dd[j + 2]);
                u64 s2 = fma2(ey, ey, mul2(ex, ex));             // (P, T)
                acc2 = add2(acc2, s2);                           // sum P, sum T
                float p2, t2;
                unpack2(s2, p2, t2);
                accD += fsqrt_approx(p2 * t2);                   // sqrt(P)*sqrt(T)
            }
        }

        // sum (pe - te)^2 = sum P + sum T - 2 sum sqrt(P*T)
        {
            float aP, aT;
            unpack2(acc2, aP, aT);
            acc = aP + aT - 2.0f * accD;
        }

        float ws = warp_reduce_sum(acc);
        if (lane == 0) sred[wid] = ws;
        __syncthreads();
        if (wid == 0) {
            float v = (lane < 8) ? sred[lane] : 0.0f;
            v = warp_reduce_sum(v);
            if (lane == 0) g_edge_partials[bid] = v;
        }
    }

    // ---- grid-wide completion; last block reduces everything ----
    __threadfence();
    if (tid == 0) {
        unsigned int prev = atomicAdd(&g_done_count, 1u);
        s_last = (prev == TOTAL_BLOCKS - 1);
    }
    __syncthreads();
    if (!s_last) return;

    float e = 0.0f, kv = 0.0f;
    for (int i = tid; i < N_EDGE_BLOCKS; i += 256) e += g_edge_partials[i];
    if (tid < KD_BLOCKS) kv = g_kd_partials[tid];

    __shared__ float se[8], sk[8];
    float we = warp_reduce_sum(e);
    float wk = warp_reduce_sum(kv);
    if (lane == 0) { se[wid] = we; sk[wid] = wk; }
    __syncthreads();
    if (wid == 0) {
        float ve = (lane < 8) ? se[lane] : 0.0f;
        float vk = (lane < 8) ? sk[lane] : 0.0f;
        ve = warp_reduce_sum(ve);
        vk = warp_reduce_sum(vk);
        if (lane == 0) {
            float edge_loss = ve * (1.0f / ((float)IMG_W * (float)IMG_H));
            float constraint = vk / (float)K;
            out[0] = 1.0f * edge_loss + 0.5f * constraint;
            g_done_count = 0;
        }
    }
}

// ---------------------------------------------------------------------------
extern "C" void kernel_launch(void* const* d_in, const int* in_sizes, int n_in,
                              void* d_out, int out_size) {
    const float* kp   = (const float*)d_in[0];
    const float* pred = (const float*)d_in[2];
    const float* tgt  = (const float*)d_in[3];
    const int K = in_sizes[0] / 2;

    fused_kernel<<<TOTAL_BLOCKS, 256>>>(pred, tgt, kp, K, (float*)d_out);
}